// round 1
// baseline (speedup 1.0000x reference)
#include <cuda_runtime.h>
#include <cstdint>
#include <cstdio>

// Problem dims (fixed)
#define BB 32
#define TT 1024
#define CC 512
#define DD 256
#define UU 256
#define FOURU 1024
#define MTOT (BB*TT)   // 32768

// Scratch (device globals: no cudaMalloc allowed)
__device__ float g_xin[(size_t)MTOT * DD];     // [B*T, 256]
__device__ float g_xz [(size_t)MTOT * FOURU];  // [B*T, 1024]
__device__ float g_hs [(size_t)MTOT * UU];     // [B*T, 256]

// ---------------------------------------------------------------------------
// Tiled fp32 GEMM with bias:  C[M,N] = A[M,K] @ B[K,N] + bias[N]
// BM=128, BN=64, BK=16, 256 threads, 8x4 per thread.
// All dims are exact multiples (M=32768, N in {256,1024}, K in {512,256}).
// ---------------------------------------------------------------------------
__global__ void __launch_bounds__(256)
gemm_bias_kernel(const float* __restrict__ A, const float* __restrict__ B,
                 const float* __restrict__ bias, float* __restrict__ C,
                 int M, int N, int K)
{
    __shared__ float As[16][129];   // padded: conflict-free transposed store
    __shared__ float Bs[16][64];

    const int tid = threadIdx.x;
    const int tx = tid & 15;        // 16 col groups * 4 = 64
    const int ty = tid >> 4;        // 16 row groups * 8 = 128
    const int bm = blockIdx.y * 128;
    const int bn = blockIdx.x * 64;

    float acc[8][4];
    #pragma unroll
    for (int i = 0; i < 8; i++)
        #pragma unroll
        for (int j = 0; j < 4; j++) acc[i][j] = 0.f;

    for (int k0 = 0; k0 < K; k0 += 16) {
        // Load A tile 128x16 (2 float4 per thread), store transposed
        #pragma unroll
        for (int l = 0; l < 2; l++) {
            int id = tid + 256 * l;
            int r  = id >> 2;
            int c4 = id & 3;
            float4 v = *(const float4*)&A[(size_t)(bm + r) * K + k0 + c4 * 4];
            As[c4*4+0][r] = v.x;
            As[c4*4+1][r] = v.y;
            As[c4*4+2][r] = v.z;
            As[c4*4+3][r] = v.w;
        }
        // Load B tile 16x64 (1 float4 per thread)
        {
            int r  = tid >> 4;
            int c4 = tid & 15;
            float4 v = *(const float4*)&B[(size_t)(k0 + r) * N + bn + c4 * 4];
            *(float4*)&Bs[r][c4 * 4] = v;
        }
        __syncthreads();

        #pragma unroll
        for (int kk = 0; kk < 16; kk++) {
            float a[8], b[4];
            #pragma unroll
            for (int i = 0; i < 8; i++) a[i] = As[kk][ty * 8 + i];
            #pragma unroll
            for (int j = 0; j < 4; j++) b[j] = Bs[kk][tx * 4 + j];
            #pragma unroll
            for (int i = 0; i < 8; i++)
                #pragma unroll
                for (int j = 0; j < 4; j++)
                    acc[i][j] = fmaf(a[i], b[j], acc[i][j]);
        }
        __syncthreads();
    }

    float bv[4];
    #pragma unroll
    for (int j = 0; j < 4; j++) bv[j] = bias[bn + tx * 4 + j];

    #pragma unroll
    for (int i = 0; i < 8; i++) {
        float4 o;
        o.x = acc[i][0] + bv[0];
        o.y = acc[i][1] + bv[1];
        o.z = acc[i][2] + bv[2];
        o.w = acc[i][3] + bv[3];
        *(float4*)&C[(size_t)(bm + ty * 8 + i) * N + bn + tx * 4] = o;
    }
}

// ---------------------------------------------------------------------------
// Persistent LSTM recurrence.
// 16 clusters of 8 CTAs; each cluster owns 2 batches.
// CTA rank r owns units u in [r*32, r*32+32) -> global gate columns
// {u, 256+u, 512+u, 768+u}. Weight slice [256 x 128] held in registers
// (512 threads x 64 w regs). h double-buffered in smem; per step each CTA
// broadcasts its 32 new h values per batch to all 8 peers via DSMEM, then one
// cluster barrier.
// ---------------------------------------------------------------------------
__device__ __forceinline__ void st_cluster_f32(uint32_t laddr, uint32_t peer, float v) {
    asm volatile(
        "{\n\t"
        ".reg .b32 ra;\n\t"
        "mapa.shared::cluster.u32 ra, %0, %1;\n\t"
        "st.shared::cluster.f32 [ra], %2;\n\t"
        "}"
        :: "r"(laddr), "r"(peer), "f"(v) : "memory");
}

__device__ __forceinline__ void cluster_sync_() {
    asm volatile("barrier.cluster.arrive.aligned;" ::: "memory");
    asm volatile("barrier.cluster.wait.aligned;" ::: "memory");
}

__device__ __forceinline__ float sigmoidf_(float x) {
    return 1.f / (1.f + __expf(-x));
}

__global__ void __launch_bounds__(512, 1) __cluster_dims__(8, 1, 1)
lstm_kernel(const float* __restrict__ xz, const float* __restrict__ rec,
            float* __restrict__ hs)
{
    __shared__ float h_sh[2][2][256];   // [phase][batch][unit]
    __shared__ float part[4][2][128];   // [kgroup][batch][localcol]
    __shared__ float zsh[2][128];
    __shared__ float c_sh[2][32];

    const int tid = threadIdx.x;
    const int col = tid & 127;          // local gate column 0..127
    const int kg  = tid >> 7;           // k group 0..3 (64 k's each)

    uint32_t rank;
    asm("mov.u32 %0, %%cluster_ctarank;" : "=r"(rank));
    const int clus = blockIdx.x >> 3;
    const int b0   = clus * 2;

    const int g    = col >> 5;          // gate 0..3 (i,f,g,o)
    const int jloc = col & 31;          // local unit 0..31
    const int gcol = (int)rank * 32 + jloc + (g << 8);   // global column in [0,1024)

    // Load weight slice into registers: w[kk] = rec[kg*64+kk][gcol]
    float w[64];
    #pragma unroll
    for (int kk = 0; kk < 64; kk++)
        w[kk] = rec[(size_t)(kg * 64 + kk) * FOURU + gcol];

    // init shared state
    for (int i = tid; i < 2 * 2 * 256; i += 512) ((float*)h_sh)[i] = 0.f;
    if (tid < 64) c_sh[tid >> 5][tid & 31] = 0.f;
    __syncthreads();
    cluster_sync_();   // everyone's smem initialized before any peer writes

    // prefetch xz for t=0 (threads 0..255: b = tid>>7)
    float rxz = 0.f;
    if (tid < 256)
        rxz = __ldg(&xz[((size_t)(b0 + (tid >> 7)) * TT + 0) * FOURU + gcol]);

    int pp = 0;
    for (int t = 0; t < TT; t++) {
        // ---- phase A: partial dot products over this thread's 64 k's ----
        float acc0 = 0.f, acc1 = 0.f;
        const float* h0 = &h_sh[pp][0][kg * 64];
        const float* h1 = &h_sh[pp][1][kg * 64];
        #pragma unroll
        for (int q = 0; q < 16; q++) {
            float4 ha = *(const float4*)(h0 + 4 * q);
            float4 hb = *(const float4*)(h1 + 4 * q);
            acc0 = fmaf(w[4*q+0], ha.x, acc0);
            acc0 = fmaf(w[4*q+1], ha.y, acc0);
            acc0 = fmaf(w[4*q+2], ha.z, acc0);
            acc0 = fmaf(w[4*q+3], ha.w, acc0);
            acc1 = fmaf(w[4*q+0], hb.x, acc1);
            acc1 = fmaf(w[4*q+1], hb.y, acc1);
            acc1 = fmaf(w[4*q+2], hb.z, acc1);
            acc1 = fmaf(w[4*q+3], hb.w, acc1);
        }
        part[kg][0][col] = acc0;
        part[kg][1][col] = acc1;

        // prefetch next timestep's xz while we reduce (hides DRAM latency)
        float rxz_next = 0.f;
        if (tid < 256 && t + 1 < TT)
            rxz_next = __ldg(&xz[((size_t)(b0 + (tid >> 7)) * TT + (t + 1)) * FOURU + gcol]);

        __syncthreads();

        // ---- phase B: reduce partials + add input projection ----
        if (tid < 256) {
            int b = tid >> 7;
            float z = part[0][b][col] + part[1][b][col]
                    + part[2][b][col] + part[3][b][col] + rxz;
            zsh[b][col] = z;
        }
        __syncthreads();

        // ---- phase C: gates + state update + DSMEM h broadcast ----
        if (tid < 64) {
            int b  = tid >> 5;
            int jj = tid & 31;
            float zi = zsh[b][jj];
            float zf = zsh[b][32 + jj];
            float zg = zsh[b][64 + jj];
            float zo = zsh[b][96 + jj];
            float ig = sigmoidf_(zi);
            float fg = sigmoidf_(zf);
            float gg = tanhf(zg);
            float og = sigmoidf_(zo);
            float c  = fmaf(fg, c_sh[b][jj], ig * gg);
            c_sh[b][jj] = c;
            float h  = og * tanhf(c);

            // output h
            hs[((size_t)(b0 + b) * TT + t) * UU + (int)rank * 32 + jj] = h;

            // broadcast h into next-phase buffer of every CTA in the cluster
            int np = pp ^ 1;
            uint32_t laddr =
                (uint32_t)__cvta_generic_to_shared(&h_sh[np][b][(int)rank * 32 + jj]);
            #pragma unroll
            for (uint32_t p = 0; p < 8; p++)
                st_cluster_f32(laddr, p, h);
        }

        rxz = rxz_next;
        pp ^= 1;
        cluster_sync_();   // all h writes visible before next step's reads
    }
}

// ---------------------------------------------------------------------------
// Launch
// ---------------------------------------------------------------------------
extern "C" void kernel_launch(void* const* d_in, const int* in_sizes, int n_in,
                              void* d_out, int out_size)
{
    const float* x      = (const float*)d_in[0];
    const float* w_in   = (const float*)d_in[1];
    const float* b_in   = (const float*)d_in[2];
    const float* kern   = (const float*)d_in[3];
    const float* rec    = (const float*)d_in[4];
    const float* bias   = (const float*)d_in[5];
    const float* w_out  = (const float*)d_in[6];
    const float* b_out  = (const float*)d_in[7];
    float* out = (float*)d_out;

    float *xin, *xz, *hs;
    cudaGetSymbolAddress((void**)&xin, g_xin);
    cudaGetSymbolAddress((void**)&xz,  g_xz);
    cudaGetSymbolAddress((void**)&hs,  g_hs);

    // xin = x @ w_in + b_in            [32768,512] @ [512,256]
    gemm_bias_kernel<<<dim3(DD / 64, MTOT / 128), 256>>>(x, w_in, b_in, xin,
                                                         MTOT, DD, CC);
    // xz = xin @ kernel + bias         [32768,256] @ [256,1024]
    gemm_bias_kernel<<<dim3(FOURU / 64, MTOT / 128), 256>>>(xin, kern, bias, xz,
                                                            MTOT, FOURU, DD);
    // recurrence -> hs                 16 clusters x 8 CTAs
    lstm_kernel<<<128, 512>>>(xz, rec, hs);

    // out = hs @ w_out + b_out         [32768,256] @ [256,256]
    gemm_bias_kernel<<<dim3(UU / 64, MTOT / 128), 256>>>(hs, w_out, b_out, out,
                                                         MTOT, UU, UU);
}

// round 2
// speedup vs baseline: 1.0072x; 1.0072x over previous
#include <cuda_runtime.h>
#include <cstdint>

#define BB 32
#define TT 1024
#define CC 512
#define DD 256
#define UU 256
#define FOURU 1024
#define MTOT (BB*TT)

__device__ float g_xin[(size_t)MTOT * DD];
__device__ float g_xz [(size_t)MTOT * FOURU];
__device__ float g_hs [(size_t)MTOT * UU];

// ---------------- f32x2 helpers ----------------
__device__ __forceinline__ unsigned long long fma2(unsigned long long a,
                                                   unsigned long long b,
                                                   unsigned long long c) {
    unsigned long long d;
    asm("fma.rn.f32x2 %0, %1, %2, %3;" : "=l"(d) : "l"(a), "l"(b), "l"(c));
    return d;
}
__device__ __forceinline__ unsigned long long pack2(float lo, float hi) {
    unsigned long long d;
    asm("mov.b64 %0, {%1, %2};" : "=l"(d) : "r"(__float_as_uint(lo)), "r"(__float_as_uint(hi)));
    return d;
}
__device__ __forceinline__ float lo32(unsigned long long v) {
    return __uint_as_float((unsigned)(v & 0xffffffffull));
}
__device__ __forceinline__ float hi32(unsigned long long v) {
    return __uint_as_float((unsigned)(v >> 32));
}

// ---------------------------------------------------------------------------
// GEMM with bias, f32x2 inner product. BM=128, BN=64, BK=16, 256 thr, 8x4.
// ---------------------------------------------------------------------------
__global__ void __launch_bounds__(256)
gemm_bias_kernel(const float* __restrict__ A, const float* __restrict__ B,
                 const float* __restrict__ bias, float* __restrict__ C,
                 int M, int N, int K)
{
    __shared__ float As[16][132];   // 132: keeps 16B alignment per row
    __shared__ float Bs[16][64];

    const int tid = threadIdx.x;
    const int tx = tid & 15;
    const int ty = tid >> 4;
    const int bm = blockIdx.y * 128;
    const int bn = blockIdx.x * 64;

    unsigned long long acc2[4][4];   // [i-pair][j]
    #pragma unroll
    for (int i = 0; i < 4; i++)
        #pragma unroll
        for (int j = 0; j < 4; j++) acc2[i][j] = 0ull;

    for (int k0 = 0; k0 < K; k0 += 16) {
        #pragma unroll
        for (int l = 0; l < 2; l++) {
            int id = tid + 256 * l;
            int r  = id >> 2;
            int c4 = id & 3;
            float4 v = *(const float4*)&A[(size_t)(bm + r) * K + k0 + c4 * 4];
            As[c4*4+0][r] = v.x;
            As[c4*4+1][r] = v.y;
            As[c4*4+2][r] = v.z;
            As[c4*4+3][r] = v.w;
        }
        {
            int r  = tid >> 4;
            int c4 = tid & 15;
            float4 v = *(const float4*)&B[(size_t)(k0 + r) * N + bn + c4 * 4];
            *(float4*)&Bs[r][c4 * 4] = v;
        }
        __syncthreads();

        #pragma unroll
        for (int kk = 0; kk < 16; kk++) {
            const ulonglong2* ap = reinterpret_cast<const ulonglong2*>(&As[kk][ty * 8]);
            ulonglong2 aA = ap[0];            // rows (0,1),(2,3)
            ulonglong2 aB = ap[1];            // rows (4,5),(6,7)
            float4 bf = *(const float4*)&Bs[kk][tx * 4];
            unsigned long long bd[4];
            bd[0] = pack2(bf.x, bf.x);
            bd[1] = pack2(bf.y, bf.y);
            bd[2] = pack2(bf.z, bf.z);
            bd[3] = pack2(bf.w, bf.w);
            #pragma unroll
            for (int j = 0; j < 4; j++) {
                acc2[0][j] = fma2(aA.x, bd[j], acc2[0][j]);
                acc2[1][j] = fma2(aA.y, bd[j], acc2[1][j]);
                acc2[2][j] = fma2(aB.x, bd[j], acc2[2][j]);
                acc2[3][j] = fma2(aB.y, bd[j], acc2[3][j]);
            }
        }
        __syncthreads();
    }

    float bv[4];
    #pragma unroll
    for (int j = 0; j < 4; j++) bv[j] = bias[bn + tx * 4 + j];

    #pragma unroll
    for (int ip = 0; ip < 4; ip++) {
        float4 o0, o1;
        o0.x = lo32(acc2[ip][0]) + bv[0];
        o0.y = lo32(acc2[ip][1]) + bv[1];
        o0.z = lo32(acc2[ip][2]) + bv[2];
        o0.w = lo32(acc2[ip][3]) + bv[3];
        o1.x = hi32(acc2[ip][0]) + bv[0];
        o1.y = hi32(acc2[ip][1]) + bv[1];
        o1.z = hi32(acc2[ip][2]) + bv[2];
        o1.w = hi32(acc2[ip][3]) + bv[3];
        *(float4*)&C[(size_t)(bm + ty * 8 + ip * 2 + 0) * N + bn + tx * 4] = o0;
        *(float4*)&C[(size_t)(bm + ty * 8 + ip * 2 + 1) * N + bn + tx * 4] = o1;
    }
}

// ---------------------------------------------------------------------------
// LSTM recurrence: 16 clusters x 8 CTAs, 512 thr/CTA.
// tid = kg*128 + col; kg in 0..3 (64 k each); col -> unit=col>>2, gate=col&3.
// Per-step sync via st.async + transaction mbarriers (no cluster barrier).
// ---------------------------------------------------------------------------
__device__ __forceinline__ uint32_t mapa_(uint32_t addr, uint32_t rank) {
    uint32_t r;
    asm("mapa.shared::cluster.u32 %0, %1, %2;" : "=r"(r) : "r"(addr), "r"(rank));
    return r;
}
__device__ __forceinline__ void st_async_f32(uint32_t rdata, float v, uint32_t rmbar) {
    asm volatile("st.async.shared::cluster.mbarrier::complete_tx::bytes.b32 [%0], %1, [%2];"
                 :: "r"(rdata), "r"(__float_as_uint(v)), "r"(rmbar) : "memory");
}
__device__ __forceinline__ void mbar_init(uint32_t addr, uint32_t cnt) {
    asm volatile("mbarrier.init.shared.b64 [%0], %1;" :: "r"(addr), "r"(cnt) : "memory");
}
__device__ __forceinline__ void mbar_expect_tx(uint32_t addr, uint32_t tx) {
    asm volatile("mbarrier.arrive.expect_tx.shared.b64 _, [%0], %1;"
                 :: "r"(addr), "r"(tx) : "memory");
}
__device__ __forceinline__ void mbar_wait(uint32_t addr, uint32_t parity) {
    uint32_t done;
    asm volatile("{\n\t.reg .pred p;\n\t"
                 "mbarrier.try_wait.parity.acquire.cluster.shared::cta.b64 p, [%1], %2, 0x989680;\n\t"
                 "selp.b32 %0, 1, 0, p;\n\t}"
                 : "=r"(done) : "r"(addr), "r"(parity) : "memory");
    while (!done) {
        asm volatile("{\n\t.reg .pred p;\n\t"
                     "mbarrier.try_wait.parity.acquire.cluster.shared::cta.b64 p, [%1], %2, 0x989680;\n\t"
                     "selp.b32 %0, 1, 0, p;\n\t}"
                     : "=r"(done) : "r"(addr), "r"(parity) : "memory");
    }
}
__device__ __forceinline__ void cluster_sync_() {
    asm volatile("barrier.cluster.arrive.aligned;" ::: "memory");
    asm volatile("barrier.cluster.wait.aligned;" ::: "memory");
}
__device__ __forceinline__ float sigf(float x) {
    return __fdividef(1.f, 1.f + __expf(-x));
}
__device__ __forceinline__ float tanhfast(float x) {
    return __fdividef(2.f, 1.f + __expf(-2.f * x)) - 1.f;
}

__global__ void __launch_bounds__(512, 1) __cluster_dims__(8, 1, 1)
lstm_kernel(const float* __restrict__ xz, const float* __restrict__ rec,
            float* __restrict__ hs)
{
    __shared__ float h_sh[2][2][256];            // [phase][batch][unit]
    __shared__ float part[2][3][2][128];         // [phase][kg-1][batch][col]
    __shared__ alignas(8) unsigned long long mbar_sh[2];

    const int tid  = threadIdx.x;
    const int col  = tid & 127;
    const int kg   = tid >> 7;                   // 0..3
    const int gate = col & 3;
    const int unit = col >> 2;

    uint32_t rank;
    asm("mov.u32 %0, %%cluster_ctarank;" : "=r"(rank));
    const int b0 = (blockIdx.x >> 3) * 2;
    const int gcol = gate * 256 + (int)rank * 32 + unit;   // column in [0,1024)

    // weights: k in [kg*64, kg*64+64), packed into 32 f32x2 regs
    unsigned long long w2[32];
    #pragma unroll
    for (int q = 0; q < 32; q++) {
        float wl = rec[(size_t)(kg * 64 + 2 * q + 0) * FOURU + gcol];
        float wh = rec[(size_t)(kg * 64 + 2 * q + 1) * FOURU + gcol];
        w2[q] = pack2(wl, wh);
    }

    // init
    for (int i = tid; i < 2 * 2 * 256; i += 512) ((float*)h_sh)[i] = 0.f;
    uint32_t mbar_addr0 = (uint32_t)__cvta_generic_to_shared(&mbar_sh[0]);
    if (tid == 0) {
        mbar_init(mbar_addr0, 1);
        mbar_init(mbar_addr0 + 8, 1);
    }
    __syncthreads();
    cluster_sync_();   // mbar init + h_sh zeros visible cluster-wide

    float c0 = 0.f, c1 = 0.f;
    float xz0 = 0.f, xz1 = 0.f;
    if (kg == 0) {
        xz0 = __ldg(&xz[((size_t)(b0 + 0) * TT + 0) * FOURU + gcol]);
        xz1 = __ldg(&xz[((size_t)(b0 + 1) * TT + 0) * FOURU + gcol]);
    }

    uint32_t ldata = (uint32_t)__cvta_generic_to_shared(&h_sh[0][0][(int)rank * 32 + unit]);
    const uint32_t HPHASE = 2 * 256 * 4;   // bytes between phase buffers
    const uint32_t HBATCH = 256 * 4;       // bytes between batches

    int ph[2] = {0, 0};

    for (int t = 0; t < TT; t++) {
        const int pp = t & 1;
        if (t > 0) {
            mbar_wait(mbar_addr0 + 8u * pp, ph[pp]);
            // note: all 512 threads wait; parity flipped below by each thread
        }
        if (t > 0 && tid == 0) {}   // (parity tracked per-thread)
        if (t > 0) ph[pp] ^= 1;
        if (tid == 0 && t + 1 < TT)
            mbar_expect_tx(mbar_addr0 + 8u * (pp ^ 1), 2048);

        // ---- phase A: f32x2 dot over this thread's 64 k's, both batches ----
        unsigned long long a0 = 0ull, a1 = 0ull, a2 = 0ull, a3 = 0ull;
        const ulonglong2* h0p = reinterpret_cast<const ulonglong2*>(&h_sh[pp][0][kg * 64]);
        const ulonglong2* h1p = reinterpret_cast<const ulonglong2*>(&h_sh[pp][1][kg * 64]);
        #pragma unroll
        for (int q = 0; q < 16; q++) {
            ulonglong2 hv0 = h0p[q];
            ulonglong2 hv1 = h1p[q];
            a0 = fma2(w2[2 * q + 0], hv0.x, a0);
            a1 = fma2(w2[2 * q + 1], hv0.y, a1);
            a2 = fma2(w2[2 * q + 0], hv1.x, a2);
            a3 = fma2(w2[2 * q + 1], hv1.y, a3);
        }
        float s0 = (lo32(a0) + hi32(a0)) + (lo32(a1) + hi32(a1));
        float s1 = (lo32(a2) + hi32(a2)) + (lo32(a3) + hi32(a3));

        if (kg > 0) {
            part[pp][kg - 1][0][col] = s0;
            part[pp][kg - 1][1][col] = s1;
        }

        // prefetch next xz while partials settle
        float nxz0 = 0.f, nxz1 = 0.f;
        if (kg == 0 && t + 1 < TT) {
            nxz0 = __ldg(&xz[((size_t)(b0 + 0) * TT + (t + 1)) * FOURU + gcol]);
            nxz1 = __ldg(&xz[((size_t)(b0 + 1) * TT + (t + 1)) * FOURU + gcol]);
        }
        __syncthreads();

        if (kg == 0) {
            float z0 = s0 + part[pp][0][0][col] + part[pp][1][0][col]
                          + part[pp][2][0][col] + xz0;
            float z1 = s1 + part[pp][0][1][col] + part[pp][1][1][col]
                          + part[pp][2][1][col] + xz1;

            const int lane = tid & 31;
            const int base = lane & ~3;
            float zi0 = __shfl_sync(0xffffffffu, z0, base + 0);
            float zf0 = __shfl_sync(0xffffffffu, z0, base + 1);
            float zg0 = __shfl_sync(0xffffffffu, z0, base + 2);
            float zo0 = __shfl_sync(0xffffffffu, z0, base + 3);
            float zi1 = __shfl_sync(0xffffffffu, z1, base + 0);
            float zf1 = __shfl_sync(0xffffffffu, z1, base + 1);
            float zg1 = __shfl_sync(0xffffffffu, z1, base + 2);
            float zo1 = __shfl_sync(0xffffffffu, z1, base + 3);

            c0 = sigf(zf0) * c0 + sigf(zi0) * tanhfast(zg0);
            c1 = sigf(zf1) * c1 + sigf(zi1) * tanhfast(zg1);
            float h0v = sigf(zo0) * tanhfast(c0);
            float h1v = sigf(zo1) * tanhfast(c1);

            if (gate == 0) {
                hs[((size_t)(b0 + 0) * TT + t) * UU + (int)rank * 32 + unit] = h0v;
                hs[((size_t)(b0 + 1) * TT + t) * UU + (int)rank * 32 + unit] = h1v;
                if (t + 1 < TT) {
                    const int np = pp ^ 1;
                    uint32_t lbase = ldata + (uint32_t)np * HPHASE;
                    uint32_t lmb   = mbar_addr0 + 8u * np;
                    #pragma unroll
                    for (uint32_t p = 0; p < 8; p++) {
                        uint32_t rd = mapa_(lbase, p);
                        uint32_t rm = mapa_(lmb, p);
                        st_async_f32(rd, h0v, rm);
                        st_async_f32(rd + HBATCH, h1v, rm);
                    }
                }
            }
            xz0 = nxz0;
            xz1 = nxz1;
        }
    }
    cluster_sync_();   // don't exit while peers' st.async may target us
}

// ---------------------------------------------------------------------------
extern "C" void kernel_launch(void* const* d_in, const int* in_sizes, int n_in,
                              void* d_out, int out_size)
{
    const float* x      = (const float*)d_in[0];
    const float* w_in   = (const float*)d_in[1];
    const float* b_in   = (const float*)d_in[2];
    const float* kern   = (const float*)d_in[3];
    const float* rec    = (const float*)d_in[4];
    const float* bias   = (const float*)d_in[5];
    const float* w_out  = (const float*)d_in[6];
    const float* b_out  = (const float*)d_in[7];
    float* out = (float*)d_out;

    float *xin, *xz, *hs;
    cudaGetSymbolAddress((void**)&xin, g_xin);
    cudaGetSymbolAddress((void**)&xz,  g_xz);
    cudaGetSymbolAddress((void**)&hs,  g_hs);

    gemm_bias_kernel<<<dim3(DD / 64, MTOT / 128), 256>>>(x, w_in, b_in, xin,
                                                         MTOT, DD, CC);
    gemm_bias_kernel<<<dim3(FOURU / 64, MTOT / 128), 256>>>(xin, kern, bias, xz,
                                                            MTOT, FOURU, DD);
    lstm_kernel<<<128, 512>>>(xz, rec, hs);
    gemm_bias_kernel<<<dim3(UU / 64, MTOT / 128), 256>>>(hs, w_out, b_out, out,
                                                         MTOT, UU, UU);
}